// round 1
// baseline (speedup 1.0000x reference)
#include <cuda_runtime.h>

#define FUSED_N 34603008  // 8*66*256*256

// ---------------- scratch (device globals; no allocations) ----------------
__device__ float g_xg[8*24*256*256];   // unique gauss channels (50.3 MB)
__device__ float g_out1[8*256*256];    // dynamic-conv output (1 ch/batch)
__device__ float g_pool1[8*128*9];     // pooled predictor stage 1
__device__ float g_kern[8*1323];       // predicted per-sample kernels
__device__ float g_treff[66*9];        // tr_w summed over 3 in-channels
__device__ float g_fug[66*24*9];       // fu_w gauss-half, dedup-summed
__device__ float g_W5[66*25];          // composed tr*fu 5x5 kernels
__device__ float g_cbias[66];          // fu_b + sum_m tr_b[m]*sum(fu2[o,m])
__device__ int   g_bby[24*2];          // per-unique-kernel row bbox

__device__ __forceinline__ float leaky(float v){ return v>0.f ? v : 0.2f*v; }

// ---------------- kernel 0: precompute effective weights ----------------
__global__ void k_pre(const float* __restrict__ tr_w, const float* __restrict__ tr_b,
                      const float* __restrict__ fu_w, const float* __restrict__ fu_b,
                      const float* __restrict__ w_gauss){
  __shared__ float s_tr[66*9];
  int t = threadIdx.x;
  for(int i=t;i<66*9;i+=blockDim.x){
    int m=i/9, tap=i%9;
    s_tr[i] = tr_w[(m*3+0)*9+tap]+tr_w[(m*3+1)*9+tap]+tr_w[(m*3+2)*9+tap];
  }
  __syncthreads();
  int blk = blockIdx.x;
  if(blk<66){
    int o=blk;
    if(t<9) g_treff[o*9+t]=s_tr[o*9+t];
    // dedup-summed gauss weights: channel c maps to unique u = c/22 + c/3
    for(int i=t;i<24*9;i+=blockDim.x){
      int u=i/9, tap=i%9;
      float s=0.f;
      for(int c=0;c<66;c++) if(c/22 + c/3 == u) s += fu_w[(o*132+c)*9+tap];
      g_fug[(o*24+u)*9+tap]=s;
    }
    // composed 5x5 = sum_m fu2[o,m] (*) treff[m]
    for(int i=t;i<25;i+=blockDim.x){
      int p=i/5,q=i%5;
      float s=0.f;
      for(int m=0;m<66;m++)
        for(int dy=0;dy<3;dy++){
          int ey=p-dy; if(ey<0||ey>2) continue;
          for(int dx=0;dx<3;dx++){
            int ex=q-dx; if(ex<0||ex>2) continue;
            s += fu_w[(o*132+66+m)*9+dy*3+dx]*s_tr[m*9+ey*3+ex];
          }
        }
      g_W5[o*25+i]=s;
    }
    if(t==0){
      float s=fu_b[o];
      for(int m=0;m<66;m++){
        float ws=0.f;
        for(int tap=0;tap<9;tap++) ws+=fu_w[(o*132+66+m)*9+tap];
        s += tr_b[m]*ws;
      }
      g_cbias[o]=s;
    }
  } else if(blk<90){
    int u=blk-66;
    if(t==0){
      int k = u - u/8;                      // bank kernel index
      const float* wk = w_gauss + 3*k*441;  // w_gauss[3k] == bank[k]
      int y0=21,y1=-1;
      for(int i=0;i<441;i++) if(wk[i]!=0.f){int y=i/21; if(y<y0)y0=y; if(y>y1)y1=y;}
      if(y1<0){y0=10;y1=10;}
      g_bby[u*2]=y0; g_bby[u*2+1]=y1;
    }
  }
}

// ---------------- kernel 1: p1 11x11 conv + leaky + adaptive pool (fused) ----------------
// grid: (bin 0..8, ch-chunk 0..7 [16ch], batch 0..7); one pooled scalar per (b,ch,bin)
__global__ void k_p1pool(const float* __restrict__ x, const float* __restrict__ p1_w,
                         const float* __restrict__ p1_b){
  extern __shared__ float s_x[];          // 3 * ih * iw (compact)
  __shared__ float s_w[16*363];
  __shared__ float s_acc[16];
  int bin = blockIdx.x;
  int chunk = blockIdx.y;
  int b = blockIdx.z;
  int bi = bin/3, bj = bin%3;
  int hs = bi*250/3,  he = ((bi+1)*250+2)/3;
  int ws = bj*250/3,  we = ((bj+1)*250+2)/3;
  int bh = he-hs, bw = we-ws;
  int ih = bh+10, iw = bw+10;
  int t = threadIdx.x;
  int tot = 3*ih*iw;
  for(int i=t;i<tot;i+=256){
    int c=i/(ih*iw); int r=i%(ih*iw); int ly=r/iw, lx=r%iw;
    int gy=hs-2+ly, gx=ws-2+lx;
    float v=0.f;
    if(gy>=0&&gy<256&&gx>=0&&gx<256) v = x[((b*3+c)*256+gy)*256+gx];
    s_x[i]=v;
  }
  int ch0 = chunk*16;
  for(int i=t;i<16*363;i+=256) s_w[i]=p1_w[ch0*363+i];
  if(t<16) s_acc[t]=0.f;
  __syncthreads();
  int nseg = (bw+11)/12;
  int tpc = bh*nseg;
  int total = 16*tpc;
  for(int task=t;task<total;task+=256){
    int cc = task/tpc; int r=task%tpc; int oy=r/nseg, sg=r%nseg;
    int ox0 = sg*12;
    float acc[12];
    #pragma unroll
    for(int j=0;j<12;j++) acc[j]=0.f;
    const float* wb = s_w + cc*363;
    #pragma unroll
    for(int c=0;c<3;c++){
      const float* xb = s_x + c*ih*iw;
      for(int ky=0;ky<11;ky++){
        const float* xr = xb + (oy+ky)*iw + ox0;
        float xv[22];
        #pragma unroll
        for(int j=0;j<22;j++) xv[j]=xr[j];
        const float* wr = wb + c*121 + ky*11;
        #pragma unroll
        for(int kx=0;kx<11;kx++){
          float w = wr[kx];
          #pragma unroll
          for(int px=0;px<12;px++) acc[px] += xv[px+kx]*w;
        }
      }
    }
    float bias = p1_b[ch0+cc];
    int segw = bw-ox0; if(segw>12) segw=12;
    float ls=0.f;
    #pragma unroll
    for(int px=0;px<12;px++) if(px<segw) ls += leaky(acc[px]+bias);
    atomicAdd(&s_acc[cc], ls);
  }
  __syncthreads();
  if(t<16) g_pool1[(b*128+ch0+t)*9 + bin] = s_acc[t] / (float)(bh*bw);
}

// ---------------- kernel 2: predictor tail (p2 -> pool -> p3 -> softmax -> kern) ----------------
__global__ void k_pred(const float* __restrict__ p2_w, const float* __restrict__ p3_w){
  int b = blockIdx.x;
  int t = threadIdx.x; // 512
  __shared__ float s_h1[128*9];
  __shared__ float s_h3[441*3];
  __shared__ float s_h4[441*3];
  __shared__ float s_red[3];
  for(int i=t;i<1152;i+=512) s_h1[i]=g_pool1[b*1152+i];
  __syncthreads();
  for(int j=t;j<441;j+=512){
    float acc[9];
    #pragma unroll
    for(int s=0;s<9;s++) acc[s]=0.f;
    const float* wr = p2_w + j*128;
    for(int i=0;i<128;i++){
      float w=wr[i];
      #pragma unroll
      for(int s=0;s<9;s++) acc[s]+=w*s_h1[i*9+s];
    }
    #pragma unroll
    for(int s=0;s<9;s++) acc[s]=leaky(acc[s]);
    #pragma unroll
    for(int r2=0;r2<3;r2++)
      s_h3[j*3+r2] = (acc[r2*3]+acc[r2*3+1]+acc[r2*3+2])*(1.f/3.f);
  }
  __syncthreads();
  for(int q=t;q<441;q+=512){
    float a0=0,a1=0,a2=0;
    const float* wr = p3_w + q*441;
    for(int j=0;j<441;j++){
      float w=wr[j];
      a0+=w*s_h3[j*3+0]; a1+=w*s_h3[j*3+1]; a2+=w*s_h3[j*3+2];
    }
    s_h4[q*3+0]=a0; s_h4[q*3+1]=a1; s_h4[q*3+2]=a2;
  }
  __syncthreads();
  if(t<3){
    float mx=-1e30f;
    for(int q=0;q<441;q++) mx=fmaxf(mx, s_h4[q*3+t]);
    s_red[t]=mx;
  }
  __syncthreads();
  for(int i=t;i<1323;i+=512) s_h4[i]=expf(s_h4[i]-s_red[i%3]);
  __syncthreads();
  if(t<3){
    float sm2=0.f;
    for(int q=0;q<441;q++) sm2+=s_h4[q*3+t];
    s_red[t]=1.f/sm2;
  }
  __syncthreads();
  for(int i=t;i<1323;i+=512) g_kern[b*1323+i]=s_h4[i]*s_red[i%3];
}

// ---------------- kernel 3: dynamic per-sample 3x21x21 conv ----------------
__global__ void k_dyn(const float* __restrict__ x){
  __shared__ float s_k[1323];
  __shared__ float s_x[3*52*52];
  int tile = blockIdx.x;
  int b = blockIdx.y;
  int y0 = (tile/8)*32, x0=(tile%8)*32;
  int t = threadIdx.x;
  for(int i=t;i<1323;i+=256) s_k[i]=g_kern[b*1323+i];
  for(int i=t;i<3*52*52;i+=256){
    int c=i/2704, r=i%2704, ly=r/52, lx=r%52;
    int gy=y0-10+ly, gx=x0-10+lx;
    float v=0.f;
    if(gy>=0&&gy<256&&gx>=0&&gx<256) v=x[((b*3+c)*256+gy)*256+gx];
    s_x[i]=v;
  }
  __syncthreads();
  int ty=t/8, tx4=(t%8)*4;
  float acc[4]={0,0,0,0};
  for(int c=0;c<3;c++){
    const float* xb = s_x + c*2704;
    for(int ky=0;ky<21;ky++){
      const float* xr = xb + (ty+ky)*52 + tx4;
      float xv[24];
      #pragma unroll
      for(int j=0;j<24;j++) xv[j]=xr[j];
      const float* kr = s_k + c*441 + ky*21;
      #pragma unroll
      for(int kx=0;kx<21;kx++){
        float w=kr[kx];
        #pragma unroll
        for(int px=0;px<4;px++) acc[px]+=xv[px+kx]*w;
      }
    }
  }
  int y=y0+ty;
  #pragma unroll
  for(int px=0;px<4;px++) g_out1[(b*256+y)*256 + x0+tx4+px]=acc[px];
}

// ---------------- kernel 4: gauss bank conv, 24 unique channels, row-bbox ----------------
__global__ void k_gauss(const float* __restrict__ x, const float* __restrict__ w_gauss){
  __shared__ float s_x[52*52];
  __shared__ float s_w[441];
  int tile = blockIdx.x;
  int u = blockIdx.y;
  int b = blockIdx.z;
  int y0=(tile/8)*32, x0=(tile%8)*32;
  int t=threadIdx.x;
  int g = u/8, k = u - u/8;
  const float* wk = w_gauss + 3*k*441;
  for(int i=t;i<441;i+=256) s_w[i]=wk[i];
  for(int i=t;i<2704;i+=256){
    int ly=i/52, lx=i%52;
    int gy=y0-10+ly, gx=x0-10+lx;
    float v=0.f;
    if(gy>=0&&gy<256&&gx>=0&&gx<256) v=x[((b*3+g)*256+gy)*256+gx];
    s_x[i]=v;
  }
  __syncthreads();
  int ky0=g_bby[u*2], ky1=g_bby[u*2+1];
  int ty=t/8, tx4=(t%8)*4;
  float acc[4]={0,0,0,0};
  for(int ky=ky0;ky<=ky1;ky++){
    const float* xr = s_x + (ty+ky)*52 + tx4;
    float xv[24];
    #pragma unroll
    for(int j=0;j<24;j++) xv[j]=xr[j];
    const float* kr = s_w + ky*21;
    #pragma unroll
    for(int kx=0;kx<21;kx++){
      float w=kr[kx];
      #pragma unroll
      for(int px=0;px<4;px++) acc[px]+=xv[px+kx]*w;
    }
  }
  int y=y0+ty;
  #pragma unroll
  for(int px=0;px<4;px++) g_xg[((b*24+u)*256+y)*256 + x0+tx4+px]=acc[px];
}

// ---------------- kernel 5: ax_out 3x3 conv ----------------
__global__ void k_ax(const float* __restrict__ x, const float* __restrict__ cs_w,
                     const float* __restrict__ cs_b, float* __restrict__ out){
  int b=blockIdx.y;
  int p=blockIdx.x*256+threadIdx.x;
  int y=p/256, xx=p%256;
  float acc[3]={cs_b[0],cs_b[1],cs_b[2]};
  #pragma unroll
  for(int ic=0;ic<3;ic++){
    #pragma unroll
    for(int ky=0;ky<3;ky++){
      int gy=y+ky-1; if(gy<0||gy>255) continue;
      #pragma unroll
      for(int kx=0;kx<3;kx++){
        int gx=xx+kx-1; if(gx<0||gx>255) continue;
        float v=x[((b*3+ic)*256+gy)*256+gx];
        #pragma unroll
        for(int o=0;o<3;o++) acc[o]+=v*cs_w[(o*3+ic)*9+ky*3+kx];
      }
    }
  }
  #pragma unroll
  for(int o=0;o<3;o++) out[FUSED_N + ((b*3+o)*256+y)*256+xx]=acc[o];
}

// ---------------- kernel 6: fused conv (24ch 3x3 + composed 5x5 + bias) ----------------
__global__ void k_fused(float* __restrict__ out){
  extern __shared__ float sm[];
  float* s_xg = sm;            // 24*34*34
  float* s_o1 = sm + 24*34*34; // 36*36
  __shared__ float s_w[6*24*9];
  __shared__ float s_w5[6*25];
  __shared__ float s_cb[6];
  int tile=blockIdx.x, chunk=blockIdx.y, b=blockIdx.z;
  int oc0=chunk*6;
  int y0=(tile/8)*32, x0=(tile%8)*32;
  int t=threadIdx.x;
  for(int i=t;i<24*34*34;i+=256){
    int u=i/1156, r=i%1156, ly=r/34, lx=r%34;
    int gy=y0-1+ly, gx=x0-1+lx;
    float v=0.f;
    if(gy>=0&&gy<256&&gx>=0&&gx<256) v=g_xg[((b*24+u)*256+gy)*256+gx];
    s_xg[i]=v;
  }
  for(int i=t;i<1296;i+=256){
    int ly=i/36, lx=i%36;
    int gy=y0-2+ly, gx=x0-2+lx;
    float v=0.f;
    if(gy>=0&&gy<256&&gx>=0&&gx<256) v=g_out1[(b*256+gy)*256+gx];
    s_o1[i]=v;
  }
  for(int i=t;i<6*24*9;i+=256) s_w[i]=g_fug[oc0*24*9 + i];
  if(t<150) s_w5[t]=g_W5[oc0*25+t];
  if(t<6) s_cb[t]=g_cbias[oc0+t];
  __syncthreads();
  int ty=t/8, tx4=(t%8)*4;
  float acc[6][4];
  #pragma unroll
  for(int o=0;o<6;o++){
    #pragma unroll
    for(int px=0;px<4;px++) acc[o][px]=s_cb[o];
  }
  for(int u=0;u<24;u++){
    const float* xb = s_xg + u*1156;
    #pragma unroll
    for(int ky=0;ky<3;ky++){
      const float* xr = xb + (ty+ky)*34 + tx4;
      float xv[6];
      #pragma unroll
      for(int j=0;j<6;j++) xv[j]=xr[j];
      #pragma unroll
      for(int o=0;o<6;o++){
        const float* wr = s_w + (o*24+u)*9 + ky*3;
        float w0=wr[0], w1=wr[1], w2=wr[2];
        #pragma unroll
        for(int px=0;px<4;px++) acc[o][px] += xv[px]*w0 + xv[px+1]*w1 + xv[px+2]*w2;
      }
    }
  }
  #pragma unroll
  for(int ky=0;ky<5;ky++){
    const float* xr = s_o1 + (ty+ky)*36 + tx4;
    float xv[8];
    #pragma unroll
    for(int j=0;j<8;j++) xv[j]=xr[j];
    #pragma unroll
    for(int o=0;o<6;o++){
      const float* wr=s_w5+o*25+ky*5;
      #pragma unroll
      for(int kx=0;kx<5;kx++){
        float w=wr[kx];
        #pragma unroll
        for(int px=0;px<4;px++) acc[o][px]+=xv[px+kx]*w;
      }
    }
  }
  int y=y0+ty;
  #pragma unroll
  for(int o=0;o<6;o++){
    #pragma unroll
    for(int px=0;px<4;px++)
      out[((b*66+oc0+o)*256+y)*256 + x0+tx4+px]=acc[o][px];
  }
}

// ---------------- kernel 7: exact recompute of the 1-px border ring ----------------
__device__ __forceinline__ void ringpos(int rp,int&y,int&x){
  if(rp<256){y=0;x=rp;}
  else if(rp<512){y=255;x=rp-256;}
  else if(rp<766){y=rp-511;x=0;}
  else {y=rp-765;x=255;}
}

__global__ void k_ring(const float* __restrict__ tr_b, const float* __restrict__ fu_w,
                       const float* __restrict__ fu_b, float* __restrict__ out){
  __shared__ float s_xaf[8*9*66];   // per-pixel 3x3 x_af taps, all 66 channels
  int chunk=blockIdx.x, b=blockIdx.y;
  int t=threadIdx.x;
  for(int idx=t;idx<8*9*66;idx+=256){
    int pi=idx/594, r=idx%594, tpos=r/66, m=r%66;
    int rp=chunk*8+pi;
    float v=0.f;
    if(rp<1020){
      int y,x; ringpos(rp,y,x);
      int p=y+tpos/3-1, q=x+tpos%3-1;
      if(p>=0&&p<256&&q>=0&&q<256){
        v=tr_b[m];
        #pragma unroll
        for(int tap=0;tap<9;tap++){
          int yy=p+tap/3-1, xx=q+tap%3-1;
          if(yy>=0&&yy<256&&xx>=0&&xx<256)
            v += g_treff[m*9+tap]*g_out1[(b*256+yy)*256+xx];
        }
      }
    }
    s_xaf[idx]=v;
  }
  __syncthreads();
  for(int oi=t;oi<528;oi+=256){
    int o=oi>>3, pi=oi&7;
    int rp=chunk*8+pi;
    if(rp>=1020) continue;
    int y,x; ringpos(rp,y,x);
    float acc=fu_b[o];
    for(int u=0;u<24;u++){
      #pragma unroll
      for(int tap=0;tap<9;tap++){
        int yy=y+tap/3-1, xx=x+tap%3-1;
        if(yy>=0&&yy<256&&xx>=0&&xx<256)
          acc += g_fug[(o*24+u)*9+tap]*g_xg[((b*24+u)*256+yy)*256+xx];
      }
    }
    const float* sx = s_xaf + pi*594;
    for(int m=0;m<66;m++){
      const float* wr = fu_w + (o*132+66+m)*9;
      #pragma unroll
      for(int tap=0;tap<9;tap++) acc += wr[tap]*sx[tap*66+m];
    }
    out[((b*66+o)*256+y)*256+x]=acc;
  }
}

// ---------------- launch ----------------
extern "C" void kernel_launch(void* const* d_in, const int* in_sizes, int n_in,
                              void* d_out, int out_size){
  const float* x    =(const float*)d_in[0];
  const float* wg   =(const float*)d_in[1];
  const float* p1_w =(const float*)d_in[2];
  const float* p1_b =(const float*)d_in[3];
  const float* p2_w =(const float*)d_in[4];
  const float* p3_w =(const float*)d_in[5];
  const float* cs_w =(const float*)d_in[6];
  const float* cs_b =(const float*)d_in[7];
  const float* tr_w =(const float*)d_in[8];
  const float* tr_b =(const float*)d_in[9];
  const float* fu_w =(const float*)d_in[10];
  const float* fu_b =(const float*)d_in[11];
  float* out=(float*)d_out;

  int smem_p1 = 3*94*94*(int)sizeof(float);              // 106032 B
  int smem_fu = (24*34*34 + 36*36)*(int)sizeof(float);   // 116160 B
  cudaFuncSetAttribute(k_p1pool, cudaFuncAttributeMaxDynamicSharedMemorySize, smem_p1);
  cudaFuncSetAttribute(k_fused,  cudaFuncAttributeMaxDynamicSharedMemorySize, smem_fu);

  k_pre   <<<90,128>>>(tr_w,tr_b,fu_w,fu_b,wg);
  k_p1pool<<<dim3(9,8,8),256,smem_p1>>>(x,p1_w,p1_b);
  k_pred  <<<8,512>>>(p2_w,p3_w);
  k_dyn   <<<dim3(64,8),256>>>(x);
  k_gauss <<<dim3(64,24,8),256>>>(x,wg);
  k_ax    <<<dim3(256,8),256>>>(x,cs_w,cs_b,out);
  k_fused <<<dim3(64,11,8),256,smem_fu>>>(out);
  k_ring  <<<dim3(128,8),256>>>(tr_b,fu_w,fu_b,out);
}

// round 2
// speedup vs baseline: 1.3614x; 1.3614x over previous
#include <cuda_runtime.h>

#define FUSED_N 34603008  // 8*66*256*256

// ---------------- scratch (device globals; no allocations) ----------------
__device__ float g_xg[8*24*256*256];   // unique gauss channels (50.3 MB)
__device__ float g_out1[8*256*256];    // dynamic-conv output (1 ch/batch)
__device__ float g_pool1[8*128*9];     // pooled predictor stage 1
__device__ float g_kern[8*1323];       // predicted per-sample kernels
__device__ float g_treff[66*9];        // tr_w summed over 3 in-channels
__device__ float g_fug[66*24*9];       // fu_w gauss-half, dedup-summed
__device__ float g_W5[66*25];          // composed tr*fu 5x5 kernels
__device__ float g_cbias[66];          // fu_b + sum_m tr_b[m]*sum(fu2[o,m])
__device__ int   g_bby[24*2];          // per-unique-kernel row bbox

__device__ __forceinline__ float leaky(float v){ return v>0.f ? v : 0.2f*v; }

// ---------------- kernel 0: precompute effective weights ----------------
__global__ void k_pre(const float* __restrict__ tr_w, const float* __restrict__ tr_b,
                      const float* __restrict__ fu_w, const float* __restrict__ fu_b,
                      const float* __restrict__ w_gauss){
  __shared__ float s_tr[66*9];
  int t = threadIdx.x;
  for(int i=t;i<66*9;i+=blockDim.x){
    int m=i/9, tap=i%9;
    s_tr[i] = tr_w[(m*3+0)*9+tap]+tr_w[(m*3+1)*9+tap]+tr_w[(m*3+2)*9+tap];
  }
  __syncthreads();
  int blk = blockIdx.x;
  if(blk<66){
    int o=blk;
    if(t<9) g_treff[o*9+t]=s_tr[o*9+t];
    for(int i=t;i<24*9;i+=blockDim.x){
      int u=i/9, tap=i%9;
      float s=0.f;
      for(int c=0;c<66;c++) if(c/22 + c/3 == u) s += fu_w[(o*132+c)*9+tap];
      g_fug[(o*24+u)*9+tap]=s;
    }
    for(int i=t;i<25;i+=blockDim.x){
      int p=i/5,q=i%5;
      float s=0.f;
      for(int m=0;m<66;m++)
        for(int dy=0;dy<3;dy++){
          int ey=p-dy; if(ey<0||ey>2) continue;
          for(int dx=0;dx<3;dx++){
            int ex=q-dx; if(ex<0||ex>2) continue;
            s += fu_w[(o*132+66+m)*9+dy*3+dx]*s_tr[m*9+ey*3+ex];
          }
        }
      g_W5[o*25+i]=s;
    }
    if(t==0){
      float s=fu_b[o];
      for(int m=0;m<66;m++){
        float ws=0.f;
        for(int tap=0;tap<9;tap++) ws+=fu_w[(o*132+66+m)*9+tap];
        s += tr_b[m]*ws;
      }
      g_cbias[o]=s;
    }
  } else if(blk<90){
    int u=blk-66;
    if(t==0){
      int k = u - u/8;
      const float* wk = w_gauss + 3*k*441;
      int y0=21,y1=-1;
      for(int i=0;i<441;i++) if(wk[i]!=0.f){int y=i/21; if(y<y0)y0=y; if(y>y1)y1=y;}
      if(y1<0){y0=10;y1=10;}
      g_bby[u*2]=y0; g_bby[u*2+1]=y1;
    }
  }
}

// ---------------- kernel 1: p1 11x11 conv + leaky + adaptive pool (fused) ----------------
// 24 px per thread for FMA density
__global__ void k_p1pool(const float* __restrict__ x, const float* __restrict__ p1_w,
                         const float* __restrict__ p1_b){
  extern __shared__ float s_x[];          // 3 * ih * iw (+ pad)
  __shared__ float s_w[16*363];
  __shared__ float s_acc[16];
  int bin = blockIdx.x;
  int chunk = blockIdx.y;
  int b = blockIdx.z;
  int bi = bin/3, bj = bin%3;
  int hs = bi*250/3,  he = ((bi+1)*250+2)/3;
  int ws = bj*250/3,  we = ((bj+1)*250+2)/3;
  int bh = he-hs, bw = we-ws;
  int ih = bh+10, iw = bw+10;
  int t = threadIdx.x;
  int tot = 3*ih*iw;
  for(int i=t;i<tot;i+=256){
    int c=i/(ih*iw); int r=i%(ih*iw); int ly=r/iw, lx=r%iw;
    int gy=hs-2+ly, gx=ws-2+lx;
    float v=0.f;
    if(gy>=0&&gy<256&&gx>=0&&gx<256) v = x[((b*3+c)*256+gy)*256+gx];
    s_x[i]=v;
  }
  // zero the pad region so no NaN/inf garbage
  for(int i=tot+t;i<tot+64;i+=256) s_x[i]=0.f;
  int ch0 = chunk*16;
  for(int i=t;i<16*363;i+=256) s_w[i]=p1_w[ch0*363+i];
  if(t<16) s_acc[t]=0.f;
  __syncthreads();
  int nseg = (bw+23)/24;
  int tpc = bh*nseg;
  int total = 16*tpc;
  for(int task=t;task<total;task+=256){
    int cc = task/tpc; int r=task%tpc; int oy=r/nseg, sg=r%nseg;
    int ox0 = sg*24;
    float acc[24];
    #pragma unroll
    for(int j=0;j<24;j++) acc[j]=0.f;
    const float* wb = s_w + cc*363;
    #pragma unroll
    for(int c=0;c<3;c++){
      const float* xb = s_x + c*ih*iw;
      for(int ky=0;ky<11;ky++){
        const float* xr = xb + (oy+ky)*iw + ox0;
        float xv[34];
        #pragma unroll
        for(int j=0;j<34;j++) xv[j]=xr[j];
        const float* wr = wb + c*121 + ky*11;
        #pragma unroll
        for(int kx=0;kx<11;kx++){
          float w = wr[kx];
          #pragma unroll
          for(int px=0;px<24;px++) acc[px] += xv[px+kx]*w;
        }
      }
    }
    float bias = p1_b[ch0+cc];
    int segw = bw-ox0; if(segw>24) segw=24;
    float ls=0.f;
    #pragma unroll
    for(int px=0;px<24;px++) if(px<segw) ls += leaky(acc[px]+bias);
    atomicAdd(&s_acc[cc], ls);
  }
  __syncthreads();
  if(t<16) g_pool1[(b*128+ch0+t)*9 + bin] = s_acc[t] / (float)(bh*bw);
}

// ---------------- kernel 2: predictor tail ----------------
__global__ void k_pred(const float* __restrict__ p2_w, const float* __restrict__ p3_w){
  int b = blockIdx.x;
  int t = threadIdx.x; // 512
  __shared__ float s_h1[128*9];
  __shared__ float s_h3[441*3];
  __shared__ float s_h4[441*3];
  __shared__ float s_red[3];
  for(int i=t;i<1152;i+=512) s_h1[i]=g_pool1[b*1152+i];
  __syncthreads();
  for(int j=t;j<441;j+=512){
    float acc[9];
    #pragma unroll
    for(int s=0;s<9;s++) acc[s]=0.f;
    const float* wr = p2_w + j*128;
    for(int i=0;i<128;i++){
      float w=wr[i];
      #pragma unroll
      for(int s=0;s<9;s++) acc[s]+=w*s_h1[i*9+s];
    }
    #pragma unroll
    for(int s=0;s<9;s++) acc[s]=leaky(acc[s]);
    #pragma unroll
    for(int r2=0;r2<3;r2++)
      s_h3[j*3+r2] = (acc[r2*3]+acc[r2*3+1]+acc[r2*3+2])*(1.f/3.f);
  }
  __syncthreads();
  for(int q=t;q<441;q+=512){
    float a0=0,a1=0,a2=0;
    const float* wr = p3_w + q*441;
    for(int j=0;j<441;j++){
      float w=wr[j];
      a0+=w*s_h3[j*3+0]; a1+=w*s_h3[j*3+1]; a2+=w*s_h3[j*3+2];
    }
    s_h4[q*3+0]=a0; s_h4[q*3+1]=a1; s_h4[q*3+2]=a2;
  }
  __syncthreads();
  if(t<3){
    float mx=-1e30f;
    for(int q=0;q<441;q++) mx=fmaxf(mx, s_h4[q*3+t]);
    s_red[t]=mx;
  }
  __syncthreads();
  for(int i=t;i<1323;i+=512) s_h4[i]=expf(s_h4[i]-s_red[i%3]);
  __syncthreads();
  if(t<3){
    float sm2=0.f;
    for(int q=0;q<441;q++) sm2+=s_h4[q*3+t];
    s_red[t]=1.f/sm2;
  }
  __syncthreads();
  for(int i=t;i<1323;i+=512) g_kern[b*1323+i]=s_h4[i]*s_red[i%3];
}

// ---------------- kernel 3: dynamic per-sample 3x21x21 conv (16 px/thread) ----------------
__global__ void k_dyn(const float* __restrict__ x){
  extern __shared__ float s_x[];   // 3*52*148
  __shared__ float s_k[1323];
  const int IW=148, CH=52*148;     // 7696
  int tile = blockIdx.x;
  int b = blockIdx.y;
  int y0 = (tile>>1)*32, x0=(tile&1)*128;
  int t = threadIdx.x;
  for(int i=t;i<1323;i+=256) s_k[i]=g_kern[b*1323+i];
  for(int i=t;i<3*CH;i+=256){
    int c=i/CH, r=i%CH, ly=r/IW, lx=r%IW;
    int gy=y0-10+ly, gx=x0-10+lx;
    float v=0.f;
    if(gy>=0&&gy<256&&gx>=0&&gx<256) v=x[((b*3+c)*256+gy)*256+gx];
    s_x[i]=v;
  }
  __syncthreads();
  int ty=t>>3, tx=(t&7)*16;
  float acc[16];
  #pragma unroll
  for(int j=0;j<16;j++) acc[j]=0.f;
  for(int c=0;c<3;c++){
    const float* xb = s_x + c*CH;
    for(int ky=0;ky<21;ky++){
      const float* xr = xb + (ty+ky)*IW + tx;
      float xv[36];
      #pragma unroll
      for(int j=0;j<36;j++) xv[j]=xr[j];
      const float* kr = s_k + c*441 + ky*21;
      #pragma unroll
      for(int kx=0;kx<21;kx++){
        float w=kr[kx];
        #pragma unroll
        for(int px=0;px<16;px++) acc[px]+=xv[px+kx]*w;
      }
    }
  }
  int y=y0+ty;
  #pragma unroll
  for(int px=0;px<16;px++) g_out1[(b*256+y)*256 + x0+tx+px]=acc[px];
}

// ---------------- kernel 4: gauss bank conv (16 px/thread, row-bbox) ----------------
__global__ void k_gauss(const float* __restrict__ x, const float* __restrict__ w_gauss){
  __shared__ float s_x[52*148];
  __shared__ float s_w[441];
  const int IW=148;
  int tile = blockIdx.x;
  int u = blockIdx.y;
  int b = blockIdx.z;
  int y0=(tile>>1)*32, x0=(tile&1)*128;
  int t=threadIdx.x;
  int g = u/8, k = u - u/8;
  const float* wk = w_gauss + 3*k*441;
  for(int i=t;i<441;i+=256) s_w[i]=wk[i];
  for(int i=t;i<52*148;i+=256){
    int ly=i/IW, lx=i%IW;
    int gy=y0-10+ly, gx=x0-10+lx;
    float v=0.f;
    if(gy>=0&&gy<256&&gx>=0&&gx<256) v=x[((b*3+g)*256+gy)*256+gx];
    s_x[i]=v;
  }
  __syncthreads();
  int ky0=g_bby[u*2], ky1=g_bby[u*2+1];
  int ty=t>>3, tx=(t&7)*16;
  float acc[16];
  #pragma unroll
  for(int j=0;j<16;j++) acc[j]=0.f;
  for(int ky=ky0;ky<=ky1;ky++){
    const float* xr = s_x + (ty+ky)*IW + tx;
    float xv[36];
    #pragma unroll
    for(int j=0;j<36;j++) xv[j]=xr[j];
    const float* kr = s_w + ky*21;
    #pragma unroll
    for(int kx=0;kx<21;kx++){
      float w=kr[kx];
      #pragma unroll
      for(int px=0;px<16;px++) acc[px]+=xv[px+kx]*w;
    }
  }
  int y=y0+ty;
  #pragma unroll
  for(int px=0;px<16;px++) g_xg[((b*24+u)*256+y)*256 + x0+tx+px]=acc[px];
}

// ---------------- kernel 5: ax_out 3x3 conv ----------------
__global__ void k_ax(const float* __restrict__ x, const float* __restrict__ cs_w,
                     const float* __restrict__ cs_b, float* __restrict__ out){
  int b=blockIdx.y;
  int p=blockIdx.x*256+threadIdx.x;
  int y=p/256, xx=p%256;
  float acc[3]={cs_b[0],cs_b[1],cs_b[2]};
  #pragma unroll
  for(int ic=0;ic<3;ic++){
    #pragma unroll
    for(int ky=0;ky<3;ky++){
      int gy=y+ky-1; if(gy<0||gy>255) continue;
      #pragma unroll
      for(int kx=0;kx<3;kx++){
        int gx=xx+kx-1; if(gx<0||gx>255) continue;
        float v=x[((b*3+ic)*256+gy)*256+gx];
        #pragma unroll
        for(int o=0;o<3;o++) acc[o]+=v*cs_w[(o*3+ic)*9+ky*3+kx];
      }
    }
  }
  #pragma unroll
  for(int o=0;o<3;o++) out[FUSED_N + ((b*3+o)*256+y)*256+xx]=acc[o];
}

// ---------------- kernel 6: fused conv — all 66 oc per block, 8px x 6oc per thread ----------------
__global__ void k_fused(float* __restrict__ out){
  extern __shared__ float sm[];
  float* s_xg = sm;                       // 24*18*66 = 28512
  float* s_o1 = sm + 28512;               // 20*68 = 1360
  float* s_wg = sm + 28512 + 1360;        // 66*24*9 = 14256
  float* s_w5 = s_wg + 14256;             // 66*25 = 1650
  float* s_cb = s_w5 + 1650;              // 66
  int tile=blockIdx.x, b=blockIdx.y;
  int y0=(tile>>2)*16, x0=(tile&3)*64;
  int t=threadIdx.x;
  for(int i=t;i<28512;i+=256){
    int u=i/1188, r=i%1188, ly=r/66, lx=r%66;
    int gy=y0-1+ly, gx=x0-1+lx;
    float v=0.f;
    if(gy>=0&&gy<256&&gx>=0&&gx<256) v=g_xg[((b*24+u)*256+gy)*256+gx];
    s_xg[i]=v;
  }
  for(int i=t;i<1360;i+=256){
    int ly=i/68, lx=i%68;
    int gy=y0-2+ly, gx=x0-2+lx;
    float v=0.f;
    if(gy>=0&&gy<256&&gx>=0&&gx<256) v=g_out1[(b*256+gy)*256+gx];
    s_o1[i]=v;
  }
  for(int i=t;i<14256;i+=256) s_wg[i]=g_fug[i];
  for(int i=t;i<1650;i+=256) s_w5[i]=g_W5[i];
  if(t<66) s_cb[t]=g_cbias[t];
  __syncthreads();
  int half=t>>7, tt=t&127;
  int ty=tt>>3, tx=(tt&7)*8;
  int yy=y0+ty, xxb=x0+tx;
  for(int chunk=0;chunk<6;chunk++){
    int ob = chunk*12 + half*6;
    if(ob+6>66) ob=60;   // duplicate-recompute of 60..65; identical writes, deterministic
    float acc[6][8];
    #pragma unroll
    for(int o6=0;o6<6;o6++){
      float cb=s_cb[ob+o6];
      #pragma unroll
      for(int px=0;px<8;px++) acc[o6][px]=cb;
    }
    for(int u=0;u<24;u++){
      const float* xb = s_xg + u*1188;
      #pragma unroll
      for(int ky=0;ky<3;ky++){
        const float* xr = xb + (ty+ky)*66 + tx;
        float xv[10];
        #pragma unroll
        for(int j=0;j<10;j++) xv[j]=xr[j];
        #pragma unroll
        for(int o6=0;o6<6;o6++){
          const float* wr = s_wg + ((ob+o6)*24+u)*9 + ky*3;
          float w0=wr[0], w1=wr[1], w2=wr[2];
          #pragma unroll
          for(int px=0;px<8;px++)
            acc[o6][px] += xv[px]*w0 + xv[px+1]*w1 + xv[px+2]*w2;
        }
      }
    }
    #pragma unroll
    for(int ky=0;ky<5;ky++){
      const float* xr = s_o1 + (ty+ky)*68 + tx;
      float xv[12];
      #pragma unroll
      for(int j=0;j<12;j++) xv[j]=xr[j];
      #pragma unroll
      for(int o6=0;o6<6;o6++){
        const float* wr = s_w5 + (ob+o6)*25 + ky*5;
        #pragma unroll
        for(int kx=0;kx<5;kx++){
          float w=wr[kx];
          #pragma unroll
          for(int px=0;px<8;px++) acc[o6][px]+=xv[px+kx]*w;
        }
      }
    }
    #pragma unroll
    for(int o6=0;o6<6;o6++){
      #pragma unroll
      for(int px=0;px<8;px++)
        out[((b*66+ob+o6)*256+yy)*256 + xxb+px]=acc[o6][px];
    }
  }
}

// ---------------- kernel 7: exact recompute of the 1-px border ring ----------------
__device__ __forceinline__ void ringpos(int rp,int&y,int&x){
  if(rp<256){y=0;x=rp;}
  else if(rp<512){y=255;x=rp-256;}
  else if(rp<766){y=rp-511;x=0;}
  else {y=rp-765;x=255;}
}

__global__ void k_ring(const float* __restrict__ tr_b, const float* __restrict__ fu_w,
                       const float* __restrict__ fu_b, float* __restrict__ out){
  __shared__ float s_xaf[8*9*66];
  int chunk=blockIdx.x, b=blockIdx.y;
  int t=threadIdx.x;
  for(int idx=t;idx<8*9*66;idx+=256){
    int pi=idx/594, r=idx%594, tpos=r/66, m=r%66;
    int rp=chunk*8+pi;
    float v=0.f;
    if(rp<1020){
      int y,x; ringpos(rp,y,x);
      int p=y+tpos/3-1, q=x+tpos%3-1;
      if(p>=0&&p<256&&q>=0&&q<256){
        v=tr_b[m];
        #pragma unroll
        for(int tap=0;tap<9;tap++){
          int yy=p+tap/3-1, xx=q+tap%3-1;
          if(yy>=0&&yy<256&&xx>=0&&xx<256)
            v += g_treff[m*9+tap]*g_out1[(b*256+yy)*256+xx];
        }
      }
    }
    s_xaf[idx]=v;
  }
  __syncthreads();
  for(int oi=t;oi<528;oi+=256){
    int o=oi>>3, pi=oi&7;
    int rp=chunk*8+pi;
    if(rp>=1020) continue;
    int y,x; ringpos(rp,y,x);
    float acc=fu_b[o];
    for(int u=0;u<24;u++){
      #pragma unroll
      for(int tap=0;tap<9;tap++){
        int yy=y+tap/3-1, xx=x+tap%3-1;
        if(yy>=0&&yy<256&&xx>=0&&xx<256)
          acc += g_fug[(o*24+u)*9+tap]*g_xg[((b*24+u)*256+yy)*256+xx];
      }
    }
    const float* sx = s_xaf + pi*594;
    for(int m=0;m<66;m++){
      const float* wr = fu_w + (o*132+66+m)*9;
      #pragma unroll
      for(int tap=0;tap<9;tap++) acc += wr[tap]*sx[tap*66+m];
    }
    out[((b*66+o)*256+y)*256+x]=acc;
  }
}

// ---------------- launch ----------------
extern "C" void kernel_launch(void* const* d_in, const int* in_sizes, int n_in,
                              void* d_out, int out_size){
  const float* x    =(const float*)d_in[0];
  const float* wg   =(const float*)d_in[1];
  const float* p1_w =(const float*)d_in[2];
  const float* p1_b =(const float*)d_in[3];
  const float* p2_w =(const float*)d_in[4];
  const float* p3_w =(const float*)d_in[5];
  const float* cs_w =(const float*)d_in[6];
  const float* cs_b =(const float*)d_in[7];
  const float* tr_w =(const float*)d_in[8];
  const float* tr_b =(const float*)d_in[9];
  const float* fu_w =(const float*)d_in[10];
  const float* fu_b =(const float*)d_in[11];
  float* out=(float*)d_out;

  int smem_p1 = (3*94*94 + 64)*(int)sizeof(float);       // 106288 B
  int smem_dy = (3*52*148)*(int)sizeof(float);           // 92352 B
  int smem_fu = (28512+1360+14256+1650+66)*(int)sizeof(float); // 183376 B
  cudaFuncSetAttribute(k_p1pool, cudaFuncAttributeMaxDynamicSharedMemorySize, smem_p1);
  cudaFuncSetAttribute(k_dyn,    cudaFuncAttributeMaxDynamicSharedMemorySize, smem_dy);
  cudaFuncSetAttribute(k_fused,  cudaFuncAttributeMaxDynamicSharedMemorySize, smem_fu);

  k_pre   <<<90,128>>>(tr_w,tr_b,fu_w,fu_b,wg);
  k_p1pool<<<dim3(9,8,8),256,smem_p1>>>(x,p1_w,p1_b);
  k_pred  <<<8,512>>>(p2_w,p3_w);
  k_dyn   <<<dim3(16,8),256,smem_dy>>>(x);
  k_gauss <<<dim3(16,24,8),256>>>(x,wg);
  k_ax    <<<dim3(256,8),256>>>(x,cs_w,cs_b,out);
  k_fused <<<dim3(64,8),256,smem_fu>>>(out);
  k_ring  <<<dim3(128,8),256>>>(tr_b,fu_w,fu_b,out);
}